// round 12
// baseline (speedup 1.0000x reference)
#include <cuda_runtime.h>
#include <cuda_bf16.h>
#include <math.h>
#include <cstdint>

constexpr int cB  = 256;
constexpr int cL  = 128;
constexpr int cH  = 512;
constexpr int cH4 = 2048;
constexpr int KCAT = 1024;
constexpr int NBLK = 128;      // persistent grid size (<= 148 SMs)

typedef __nv_bfloat16 bf16;

__device__ __align__(16) bf16  g_hb[2][cB * cH];
__device__ float g_c[cB * cH];
__device__ float g_q[cB * cH];
__device__ __align__(16) bf16  g_enc_outb[(size_t)cB * cL * cH];
__device__ __align__(16) bf16  g_enc_w1b[(size_t)cB * cL * cH];
__device__ __align__(16) bf16  g_xcatb[cB * KCAT];
__device__ __align__(16) bf16  g_Whx[(size_t)cH4 * cH];
__device__ __align__(16) bf16  g_catW[(size_t)cH4 * KCAT];
__device__ __align__(16) bf16  g_w1b[(size_t)cH * cH];
__device__ __align__(16) bf16  g_w2b[(size_t)cH * cH];
__device__ float g_Wie[cH4];
__device__ float g_Wid[cH4];
__device__ float g_be[cH4];
__device__ float g_bd[cH4];
__device__ float g_decin[cL * cB];
__device__ unsigned g_barE, g_barD;

// ---------------- math / PTX helpers ----------------
__device__ __forceinline__ float acc_tanh(float x) {
    float a = fabsf(x);
    float e = __expf(-2.0f * a);
    float r = __fdividef(1.0f - e, 1.0f + e);
    return copysignf(r, x);
}
__device__ __forceinline__ float acc_sig(float x) {
    return __fdividef(1.0f, 1.0f + __expf(-x));
}
__device__ __forceinline__ float mufu_tanh(float x) {
    float y; asm("tanh.approx.f32 %0, %1;" : "=f"(y) : "f"(x)); return y;
}
__device__ __forceinline__ void mma_bf16(float* d, const uint32_t* a, const uint32_t* b) {
    asm volatile("mma.sync.aligned.m16n8k16.row.col.f32.bf16.bf16.f32 "
                 "{%0,%1,%2,%3}, {%4,%5,%6,%7}, {%8,%9}, {%0,%1,%2,%3};"
                 : "+f"(d[0]), "+f"(d[1]), "+f"(d[2]), "+f"(d[3])
                 : "r"(a[0]), "r"(a[1]), "r"(a[2]), "r"(a[3]), "r"(b[0]), "r"(b[1]));
}
__device__ __forceinline__ uint32_t smem_u32(const void* p) {
    uint32_t a;
    asm("{ .reg .u64 t; cvta.to.shared.u64 t, %1; cvt.u32.u64 %0, t; }" : "=r"(a) : "l"(p));
    return a;
}
#define CP_ASYNC16(dst, src) \
    asm volatile("cp.async.ca.shared.global [%0], [%1], 16;" :: "r"(dst), "l"(src) : "memory")
#define CP_COMMIT() asm volatile("cp.async.commit_group;" ::: "memory")
#define CP_WAIT(n)  asm volatile("cp.async.wait_group %0;" :: "n"(n) : "memory")

// grid-wide barrier: monotonic counter, release-arrive / acquire-spin
__device__ __forceinline__ void gsync(unsigned* bar, unsigned target) {
    __syncthreads();
    if (threadIdx.x == 0) {
        __threadfence();
        atomicAdd(bar, 1u);
        unsigned v;
        do {
            asm volatile("ld.acquire.gpu.global.u32 %0, [%1];" : "=r"(v) : "l"(bar));
        } while (v < target);
    }
    __syncthreads();
}

// ---------------- prep ----------------
__global__ void prep_kernel(const int* __restrict__ xs, const int* __restrict__ as,
                            const float* __restrict__ encWi, const float* __restrict__ encWh,
                            const float* __restrict__ encB,
                            const float* __restrict__ decWi, const float* __restrict__ decWh,
                            const float* __restrict__ decB,
                            const float* __restrict__ w1, const float* __restrict__ w2) {
    int stride = gridDim.x * blockDim.x;
    const int TOT = cH4 * KCAT;
    for (int idx = blockIdx.x * blockDim.x + threadIdx.x; idx < TOT; idx += stride) {
        {   // catW: new row 4j+g <- source row g*512+j
            int nr = idx >> 10, k = idx & 1023;
            int j = nr >> 2, g = nr & 3;
            int r = g * cH + j;
            float v = (k < cH) ? decWi[r * (cH + 1) + k]
                               : decWh[r * cH + (k - cH)];
            g_catW[idx] = __float2bfloat16_rn(v);
        }
        if (idx < cH4 * cH) {
            int nr = idx >> 9, k = idx & 511;
            int j = nr >> 2, g = nr & 3;
            g_Whx[idx] = __float2bfloat16_rn(encWh[(g * cH + j) * cH + k]);
        }
        if (idx < cH * cH) {
            g_w1b[idx] = __float2bfloat16_rn(w1[idx]);
            g_w2b[idx] = __float2bfloat16_rn(w2[idx]);
        }
        if (idx < cH4) {
            int j = idx >> 2, g = idx & 3;
            g_Wie[idx] = encWi[g * cH + j];
            g_Wid[idx] = decWi[(g * cH + j) * (cH + 1) + cH];
            g_be[idx]  = encB[g * cH + j];
            g_bd[idx]  = decB[g * cH + j];
        }
        if (idx < cB * cH) { g_hb[0][idx] = __float2bfloat16_rn(0.0f); g_c[idx] = 0.0f; }
        if (idx < cL * cB) {
            int tt = idx / cB, bb = idx - tt * cB;
            g_decin[idx] = (tt == 0) ? 0.0f
                         : (float)xs[bb * cL + as[bb * cL + tt - 1]];
        }
        if (idx == 0) { g_barE = 0u; g_barD = 0u; }
    }
}

// ---------------- 4-warp MMA on one 64x64x32 chunk (smem-resident operands) ----
__device__ __forceinline__ void mma4_chunk(const bf16* aS, const bf16* wS,
                                           float (*acc)[4], int w, int g4, int q2) {
#pragma unroll
    for (int ks = 0; ks < 32; ks += 16) {
        uint32_t a[4];
        const bf16* ar = aS + (16 * w + g4) * 40 + ks + q2;
        a[0] = *(const uint32_t*)ar;
        a[1] = *(const uint32_t*)(ar + 8 * 40);
        a[2] = *(const uint32_t*)(ar + 8);
        a[3] = *(const uint32_t*)(ar + 8 * 40 + 8);
#pragma unroll
        for (int nt = 0; nt < 8; nt++) {
            uint32_t b[2];
            const bf16* br = wS + (8 * nt + g4) * 40 + ks + q2;
            b[0] = *(const uint32_t*)br;
            b[1] = *(const uint32_t*)(br + 8);
            mma_bf16(acc[nt], a, b);
        }
    }
}

// ---------------- persistent encoder: 128 LSTM steps, W resident in smem ----
__global__ __launch_bounds__(128)
void enc_persist(const int* __restrict__ xs) {
    extern __shared__ __align__(16) bf16 smem[];
    bf16* sWres = smem;              // 16 chunks x 64 x 40
    bf16* sA    = smem + 16 * 2560;  // 4 stages  x 64 x 40
    int tid = threadIdx.x, w = tid >> 5, lane = tid & 31;
    int g4 = lane >> 2, q2 = (lane & 3) * 2;
    int nb = blockIdx.x & 31, mb = blockIdx.x >> 5;
    int m0 = mb * 64, n0 = nb * 64;
    uint32_t sW_u = smem_u32(sWres), sA_u = smem_u32(sA);
    int lr = tid >> 2, lc8 = (tid & 3) * 8;

    // preload resident W tile (64 rows x 512 cols)
    const bf16* Wg = g_Whx + (size_t)n0 * cH;
#pragma unroll
    for (int c = 0; c < 16; c++)
#pragma unroll
        for (int it = 0; it < 2; it++) {
            int r = lr + 32 * it;
            CP_ASYNC16(sW_u + (uint32_t)(c * 2560 + r * 40 + lc8) * 2,
                       Wg + (size_t)r * cH + c * 32 + lc8);
        }
    CP_COMMIT(); CP_WAIT(0);
    __syncthreads();

    unsigned target = 0;
    int cur = 0;
    for (int t = 0; t < cL; t++) {
        const bf16* Ab = g_hb[cur] + (size_t)m0 * cH;
        bf16* hout = g_hb[cur ^ 1];
        float acc[8][4];
#pragma unroll
        for (int i = 0; i < 8; i++)
#pragma unroll
            for (int j = 0; j < 4; j++) acc[i][j] = 0.0f;

#pragma unroll
        for (int pc = 0; pc < 3; pc++) {
#pragma unroll
            for (int it = 0; it < 2; it++) {
                int r = lr + 32 * it;
                CP_ASYNC16(sA_u + (uint32_t)(pc * 2560 + r * 40 + lc8) * 2,
                           Ab + (size_t)r * cH + pc * 32 + lc8);
            }
            CP_COMMIT();
        }
        for (int i = 0; i < 16; i++) {
            int rem = 15 - i;
            if (rem >= 2) { CP_WAIT(2); } else if (rem == 1) { CP_WAIT(1); } else { CP_WAIT(0); }
            __syncthreads();
            int nxt = i + 3;
            if (nxt < 16) {
                int st = nxt & 3;
#pragma unroll
                for (int it = 0; it < 2; it++) {
                    int r = lr + 32 * it;
                    CP_ASYNC16(sA_u + (uint32_t)(st * 2560 + r * 40 + lc8) * 2,
                               Ab + (size_t)r * cH + nxt * 32 + lc8);
                }
                CP_COMMIT();
            }
            mma4_chunk(sA + (i & 3) * 2560, sWres + i * 2560, acc, w, g4, q2);
        }
        __syncthreads();

        // gate epilogue: z staged in sA region (64 x 65 fp32 = 16.6 KB <= 20.5 KB)
        float* sZ = (float*)sA;
        int zr = 16 * w + g4;
#pragma unroll
        for (int nt = 0; nt < 8; nt++) {
            int col = 8 * nt + q2;
            sZ[zr * 65 + col]           = acc[nt][0];
            sZ[zr * 65 + col + 1]       = acc[nt][1];
            sZ[(zr + 8) * 65 + col]     = acc[nt][2];
            sZ[(zr + 8) * 65 + col + 1] = acc[nt][3];
        }
        __syncthreads();
#pragma unroll
        for (int i2 = 0; i2 < 8; i2++) {
            int it = tid + i2 * 128;
            int row = it >> 4, u = it & 15;
            int b = m0 + row;
            int U = (n0 >> 2) + u;
            const float* zq = sZ + row * 65 + 4 * u;
            float zi = zq[0] + g_be[4 * U + 0];
            float zf = zq[1] + g_be[4 * U + 1];
            float zg = zq[2] + g_be[4 * U + 2];
            float zo = zq[3] + g_be[4 * U + 3];
            float xt = (float)xs[b * cL + t];
            zi = fmaf(xt, g_Wie[4 * U + 0], zi);
            zf = fmaf(xt, g_Wie[4 * U + 1], zf);
            zg = fmaf(xt, g_Wie[4 * U + 2], zg);
            zo = fmaf(xt, g_Wie[4 * U + 3], zo);
            float cold = g_c[b * cH + U];
            float cn = acc_sig(zf) * cold + acc_sig(zi) * acc_tanh(zg);
            float hn = acc_sig(zo) * acc_tanh(cn);
            g_c[b * cH + U] = cn;
            bf16 hr = __float2bfloat16_rn(hn);
            hout[b * cH + U] = hr;
            g_enc_outb[(size_t)(b * cL + t) * cH + U] = hr;
        }
        cur ^= 1;
        target += NBLK;
        gsync(&g_barE, target);
    }
}

// ---------------- one-shot GEMM: enc_w1 = enc_out @ w1^T (bf16 out) ----------------
__global__ __launch_bounds__(128)
void gemm_w1() {
    __shared__ __align__(16) bf16 s[8 * 2560];
    bf16* sA = s;
    bf16* sW = s + 4 * 2560;
    int tid = threadIdx.x, w = tid >> 5, lane = tid & 31;
    int g4 = lane >> 2, q2 = (lane & 3) * 2;
    int n0 = blockIdx.x * 64, m0 = blockIdx.y * 64;
    uint32_t sA_u = smem_u32(sA), sW_u = smem_u32(sW);
    int lr = tid >> 2, lc8 = (tid & 3) * 8;
    const bf16* Ab = g_enc_outb + (size_t)m0 * cH;
    const bf16* Wb = g_w1b + (size_t)n0 * cH;

    float acc[8][4];
#pragma unroll
    for (int i = 0; i < 8; i++)
#pragma unroll
        for (int j = 0; j < 4; j++) acc[i][j] = 0.0f;

#pragma unroll
    for (int pc = 0; pc < 3; pc++) {
#pragma unroll
        for (int it = 0; it < 2; it++) {
            int r = lr + 32 * it;
            CP_ASYNC16(sA_u + (uint32_t)(pc * 2560 + r * 40 + lc8) * 2,
                       Ab + (size_t)r * cH + pc * 32 + lc8);
            CP_ASYNC16(sW_u + (uint32_t)(pc * 2560 + r * 40 + lc8) * 2,
                       Wb + (size_t)r * cH + pc * 32 + lc8);
        }
        CP_COMMIT();
    }
    for (int i = 0; i < 16; i++) {
        int rem = 15 - i;
        if (rem >= 2) { CP_WAIT(2); } else if (rem == 1) { CP_WAIT(1); } else { CP_WAIT(0); }
        __syncthreads();
        int nxt = i + 3;
        if (nxt < 16) {
            int st = nxt & 3;
#pragma unroll
            for (int it = 0; it < 2; it++) {
                int r = lr + 32 * it;
                CP_ASYNC16(sA_u + (uint32_t)(st * 2560 + r * 40 + lc8) * 2,
                           Ab + (size_t)r * cH + nxt * 32 + lc8);
                CP_ASYNC16(sW_u + (uint32_t)(st * 2560 + r * 40 + lc8) * 2,
                           Wb + (size_t)r * cH + nxt * 32 + lc8);
            }
            CP_COMMIT();
        }
        mma4_chunk(sA + (i & 3) * 2560, sW + (i & 3) * 2560, acc, w, g4, q2);
    }
    __syncthreads();

    int mrow = m0 + 16 * w + g4;
#pragma unroll
    for (int nt = 0; nt < 8; nt++) {
        int col = n0 + 8 * nt + q2;
        __nv_bfloat162 p0, p1;
        p0.x = __float2bfloat16_rn(acc[nt][0]); p0.y = __float2bfloat16_rn(acc[nt][1]);
        p1.x = __float2bfloat16_rn(acc[nt][2]); p1.y = __float2bfloat16_rn(acc[nt][3]);
        *(__nv_bfloat162*)&g_enc_w1b[(size_t)mrow * cH + col]       = p0;
        *(__nv_bfloat162*)&g_enc_w1b[(size_t)(mrow + 8) * cH + col] = p1;
    }
}

// ---------------- 8-warp pipelined GEMM helper (decoder phases) ----------------
__device__ __forceinline__ void gemm8(const bf16* __restrict__ Ab, const bf16* __restrict__ Wb,
                                      int K, int NC, float acc[2][2][4],
                                      bf16* sA, bf16* sW,
                                      int tid, int wm, int wn, int g4, int q2) {
    uint32_t sA_u = smem_u32(sA), sW_u = smem_u32(sW);
    int lr = tid >> 2, lc8 = (tid & 3) * 8;   // lr 0..63: one 16B slot per tile per chunk
#pragma unroll
    for (int i = 0; i < 2; i++)
#pragma unroll
        for (int j = 0; j < 2; j++)
#pragma unroll
            for (int k = 0; k < 4; k++) acc[i][j][k] = 0.0f;

#pragma unroll
    for (int pc = 0; pc < 3; pc++) {
        CP_ASYNC16(sA_u + (uint32_t)(pc * 2560 + lr * 40 + lc8) * 2, Ab + (size_t)lr * K + pc * 32 + lc8);
        CP_ASYNC16(sW_u + (uint32_t)(pc * 2560 + lr * 40 + lc8) * 2, Wb + (size_t)lr * K + pc * 32 + lc8);
        CP_COMMIT();
    }
    for (int i = 0; i < NC; i++) {
        int rem = NC - 1 - i;
        if (rem >= 2) { CP_WAIT(2); } else if (rem == 1) { CP_WAIT(1); } else { CP_WAIT(0); }
        __syncthreads();
        int nxt = i + 3;
        if (nxt < NC) {
            int st = nxt & 3;
            CP_ASYNC16(sA_u + (uint32_t)(st * 2560 + lr * 40 + lc8) * 2, Ab + (size_t)lr * K + nxt * 32 + lc8);
            CP_ASYNC16(sW_u + (uint32_t)(st * 2560 + lr * 40 + lc8) * 2, Wb + (size_t)lr * K + nxt * 32 + lc8);
            CP_COMMIT();
        }
        const bf16* aS = sA + (i & 3) * 2560;
        const bf16* wS = sW + (i & 3) * 2560;
#pragma unroll
        for (int ks = 0; ks < 32; ks += 16) {
            uint32_t a0[4], a1[4];
            const bf16* ar = aS + (32 * wm + g4) * 40 + ks + q2;
            a0[0] = *(const uint32_t*)ar;
            a0[1] = *(const uint32_t*)(ar + 8 * 40);
            a0[2] = *(const uint32_t*)(ar + 8);
            a0[3] = *(const uint32_t*)(ar + 8 * 40 + 8);
            const bf16* ar1 = ar + 16 * 40;
            a1[0] = *(const uint32_t*)ar1;
            a1[1] = *(const uint32_t*)(ar1 + 8 * 40);
            a1[2] = *(const uint32_t*)(ar1 + 8);
            a1[3] = *(const uint32_t*)(ar1 + 8 * 40 + 8);
#pragma unroll
            for (int nt = 0; nt < 2; nt++) {
                uint32_t b[2];
                const bf16* br = wS + (16 * wn + 8 * nt + g4) * 40 + ks + q2;
                b[0] = *(const uint32_t*)br;
                b[1] = *(const uint32_t*)(br + 8);
                mma_bf16(acc[0][nt], a0, b);
                mma_bf16(acc[1][nt], a1, b);
            }
        }
    }
    __syncthreads();
}

// ---------------- persistent decoder: 128 steps x (q | attn | bigGEMM+gates) ----
__global__ __launch_bounds__(256)
void dec_persist(const float* __restrict__ vt_p, float* __restrict__ out) {
    __shared__ __align__(16) char sbuf[41984];
    bf16* sA = (bf16*)sbuf;
    bf16* sW = sA + 4 * 2560;
    float* vts = (float*)sbuf;          // attn region (time-shared with GEMM stages)
    float* qsh = vts + 512;             // 2 x 512
    float* sc  = qsh + 1024;            // 2 x 128
    float* aj  = sc + 256;              // 2 x 128
    float* rr  = aj + 256;              // 16: rmax[8], rsum[8]

    int tid = threadIdx.x, lane = tid & 31, w8 = tid >> 5;
    int wm = w8 >> 2, wn = w8 & 3;
    int g4 = lane >> 2, q2 = (lane & 3) * 2;
    int bid = blockIdx.x;
    int half = tid >> 7, htid = tid & 127, wh = (tid >> 5) & 3;

    unsigned target = 0;
    int cur = 0;
    for (int t = 0; t < cL; t++) {
        // ---- P1: q = h @ w2^T (blocks 0..31) ----
        if (bid < 32) {
            int n0 = (bid & 7) * 64, m0 = (bid >> 3) * 64;
            float acc[2][2][4];
            gemm8(g_hb[cur] + (size_t)m0 * cH, g_w2b + (size_t)n0 * cH,
                  cH, 16, acc, sA, sW, tid, wm, wn, g4, q2);
#pragma unroll
            for (int i = 0; i < 2; i++)
#pragma unroll
                for (int nt = 0; nt < 2; nt++) {
                    int r = m0 + 32 * wm + 16 * i + g4;
                    int c = n0 + 16 * wn + 8 * nt + q2;
                    g_q[r * cH + c]           = acc[i][nt][0];
                    g_q[r * cH + c + 1]       = acc[i][nt][1];
                    g_q[(r + 8) * cH + c]     = acc[i][nt][2];
                    g_q[(r + 8) * cH + c + 1] = acc[i][nt][3];
                }
        }
        target += NBLK; gsync(&g_barD, target);

        // ---- P2: attention, rows b = 2*bid + half ----
        {
            int b = bid * 2 + half;
            for (int i = tid; i < cH; i += 256) vts[i] = vt_p[i];
            for (int i = htid; i < cH; i += 128) qsh[half * 512 + i] = g_q[b * cH + i];
            __syncthreads();

            for (int l = wh; l < cL; l += 4) {
                const uint4* row = (const uint4*)(g_enc_w1b + (size_t)(b * cL + l) * cH);
                float s = 0.0f;
#pragma unroll
                for (int it = 0; it < 2; it++) {
                    int seg = lane + 32 * it;
                    uint4 pv = row[seg];
                    int j0 = seg * 8;
                    const __nv_bfloat162* pp = (const __nv_bfloat162*)&pv;
                    float2 e0 = __bfloat1622float2(pp[0]);
                    float2 e1 = __bfloat1622float2(pp[1]);
                    float2 e2 = __bfloat1622float2(pp[2]);
                    float2 e3 = __bfloat1622float2(pp[3]);
                    const float* qb = qsh + half * 512 + j0;
                    const float* vb = vts + j0;
                    s = fmaf(vb[0], mufu_tanh(e0.x + qb[0]), s);
                    s = fmaf(vb[1], mufu_tanh(e0.y + qb[1]), s);
                    s = fmaf(vb[2], mufu_tanh(e1.x + qb[2]), s);
                    s = fmaf(vb[3], mufu_tanh(e1.y + qb[3]), s);
                    s = fmaf(vb[4], mufu_tanh(e2.x + qb[4]), s);
                    s = fmaf(vb[5], mufu_tanh(e2.y + qb[5]), s);
                    s = fmaf(vb[6], mufu_tanh(e3.x + qb[6]), s);
                    s = fmaf(vb[7], mufu_tanh(e3.y + qb[7]), s);
                }
#pragma unroll
                for (int o = 16; o > 0; o >>= 1) s += __shfl_xor_sync(0xffffffffu, s, o);
                if (lane == 0) sc[half * 128 + l] = s;
            }
            __syncthreads();

            float val = sc[half * 128 + htid];
            float m = val;
#pragma unroll
            for (int o = 16; o > 0; o >>= 1) m = fmaxf(m, __shfl_xor_sync(0xffffffffu, m, o));
            if (lane == 0) rr[half * 4 + wh] = m;
            __syncthreads();
            m = fmaxf(fmaxf(rr[half * 4], rr[half * 4 + 1]),
                      fmaxf(rr[half * 4 + 2], rr[half * 4 + 3]));
            float e = __expf(val - m);
            float ss = e;
#pragma unroll
            for (int o = 16; o > 0; o >>= 1) ss += __shfl_xor_sync(0xffffffffu, ss, o);
            if (lane == 0) rr[8 + half * 4 + wh] = ss;
            __syncthreads();
            float tot = rr[8 + half * 4] + rr[8 + half * 4 + 1]
                      + rr[8 + half * 4 + 2] + rr[8 + half * 4 + 3];
            out[((size_t)b * cL + t) * cL + htid] = val - m - __logf(tot);
            aj[half * 128 + htid] = __fdividef(e, tot);
            __syncthreads();

            const bf16* eo = g_enc_outb + (size_t)b * cL * cH;
            for (int j = htid; j < cH; j += 128) {
                float a2 = 0.0f;
#pragma unroll 8
                for (int l = 0; l < cL; l++)
                    a2 = fmaf(aj[half * 128 + l], __bfloat162float(eo[(size_t)l * cH + j]), a2);
                g_xcatb[b * KCAT + j]      = __float2bfloat16_rn(a2);
                g_xcatb[b * KCAT + cH + j] = g_hb[cur][b * cH + j];
            }
        }
        target += NBLK; gsync(&g_barD, target);

        // ---- P3: z = xcat @ catW^T + gates ----
        {
            int n0 = (bid & 31) * 64, m0 = (bid >> 5) * 64;
            float acc[2][2][4];
            gemm8(g_xcatb + (size_t)m0 * KCAT, g_catW + (size_t)n0 * KCAT,
                  KCAT, 32, acc, sA, sW, tid, wm, wn, g4, q2);
            float* sZ = (float*)sbuf;
#pragma unroll
            for (int i = 0; i < 2; i++)
#pragma unroll
                for (int nt = 0; nt < 2; nt++) {
                    int r = 32 * wm + 16 * i + g4;
                    int c = 16 * wn + 8 * nt + q2;
                    sZ[r * 65 + c]           = acc[i][nt][0];
                    sZ[r * 65 + c + 1]       = acc[i][nt][1];
                    sZ[(r + 8) * 65 + c]     = acc[i][nt][2];
                    sZ[(r + 8) * 65 + c + 1] = acc[i][nt][3];
                }
            __syncthreads();
            bf16* hout = g_hb[cur ^ 1];
#pragma unroll
            for (int i2 = 0; i2 < 4; i2++) {
                int it = tid + i2 * 256;
                int row = it >> 4, u = it & 15;
                int b = m0 + row;
                int U = (n0 >> 2) + u;
                const float* zq = sZ + row * 65 + 4 * u;
                float zi = zq[0] + g_bd[4 * U + 0];
                float zf = zq[1] + g_bd[4 * U + 1];
                float zg = zq[2] + g_bd[4 * U + 2];
                float zo = zq[3] + g_bd[4 * U + 3];
                float xt = g_decin[t * cB + b];
                zi = fmaf(xt, g_Wid[4 * U + 0], zi);
                zf = fmaf(xt, g_Wid[4 * U + 1], zf);
                zg = fmaf(xt, g_Wid[4 * U + 2], zg);
                zo = fmaf(xt, g_Wid[4 * U + 3], zo);
                float cold = g_c[b * cH + U];
                float cn = acc_sig(zf) * cold + acc_sig(zi) * acc_tanh(zg);
                float hn = acc_sig(zo) * acc_tanh(cn);
                g_c[b * cH + U] = cn;
                hout[b * cH + U] = __float2bfloat16_rn(hn);
            }
        }
        cur ^= 1;
        target += NBLK; gsync(&g_barD, target);
    }
}

// ---------------- host orchestration ----------------
extern "C" void kernel_launch(void* const* d_in, const int* in_sizes, int n_in,
                              void* d_out, int out_size) {
    const int*   xs      = (const int*)d_in[0];
    const int*   argsort = (const int*)d_in[2];
    const float* enc_Wi  = (const float*)d_in[3];
    const float* enc_Wh  = (const float*)d_in[4];
    const float* enc_b   = (const float*)d_in[5];
    const float* dec_Wi  = (const float*)d_in[6];
    const float* dec_Wh  = (const float*)d_in[7];
    const float* dec_b   = (const float*)d_in[8];
    const float* w1      = (const float*)d_in[9];
    const float* w2      = (const float*)d_in[10];
    const float* vt      = (const float*)d_in[11];
    float*       out     = (float*)d_out;

    static bool attr_done = false;
    if (!attr_done) {
        cudaFuncSetAttribute(enc_persist, cudaFuncAttributeMaxDynamicSharedMemorySize, 102400);
        attr_done = true;
    }

    prep_kernel<<<2080, 1024>>>(xs, argsort, enc_Wi, enc_Wh, enc_b,
                                dec_Wi, dec_Wh, dec_b, w1, w2);

    enc_persist<<<NBLK, 128, 102400>>>(xs);

    gemm_w1<<<dim3(cH / 64, (cB * cL) / 64), 128>>>();

    dec_persist<<<NBLK, 256>>>(vt, out);
}

// round 15
// speedup vs baseline: 1.4480x; 1.4480x over previous
#include <cuda_runtime.h>
#include <cuda_bf16.h>
#include <math.h>
#include <cstdint>

constexpr int cB  = 256;
constexpr int cL  = 128;
constexpr int cH  = 512;
constexpr int cH4 = 2048;
constexpr int KCAT = 1024;
constexpr int NBLK = 128;      // persistent encoder grid (<= 148 SMs)

typedef __nv_bfloat16 bf16;

__device__ __align__(16) bf16  g_hb[2][cB * cH];
__device__ float g_c[cB * cH];
__device__ float g_q[cB * cH];
__device__ __align__(16) bf16  g_enc_outb[(size_t)cB * cL * cH];
__device__ __align__(16) bf16  g_enc_w1b[(size_t)cB * cL * cH];
__device__ __align__(16) bf16  g_xcatb[cB * KCAT];
__device__ __align__(16) bf16  g_Whx[(size_t)cH4 * cH];
__device__ __align__(16) bf16  g_catW[(size_t)cH4 * KCAT];
__device__ __align__(16) bf16  g_w1b[(size_t)cH * cH];
__device__ __align__(16) bf16  g_w2b[(size_t)cH * cH];
__device__ float g_Wie[cH4];
__device__ float g_Wid[cH4];
__device__ float g_be[cH4];
__device__ float g_bd[cH4];
__device__ float g_decin[cL * cB];
__device__ unsigned g_barE;

// ---------------- math / PTX helpers ----------------
__device__ __forceinline__ float acc_tanh(float x) {
    float a = fabsf(x);
    float e = __expf(-2.0f * a);
    float r = __fdividef(1.0f - e, 1.0f + e);
    return copysignf(r, x);
}
__device__ __forceinline__ float acc_sig(float x) {
    return __fdividef(1.0f, 1.0f + __expf(-x));
}
__device__ __forceinline__ float mufu_tanh(float x) {
    float y; asm("tanh.approx.f32 %0, %1;" : "=f"(y) : "f"(x)); return y;
}
__device__ __forceinline__ void mma_bf16(float* d, const uint32_t* a, const uint32_t* b) {
    asm volatile("mma.sync.aligned.m16n8k16.row.col.f32.bf16.bf16.f32 "
                 "{%0,%1,%2,%3}, {%4,%5,%6,%7}, {%8,%9}, {%0,%1,%2,%3};"
                 : "+f"(d[0]), "+f"(d[1]), "+f"(d[2]), "+f"(d[3])
                 : "r"(a[0]), "r"(a[1]), "r"(a[2]), "r"(a[3]), "r"(b[0]), "r"(b[1]));
}
__device__ __forceinline__ uint32_t smem_u32(const void* p) {
    uint32_t a;
    asm("{ .reg .u64 t; cvta.to.shared.u64 t, %1; cvt.u32.u64 %0, t; }" : "=r"(a) : "l"(p));
    return a;
}
#define CP_ASYNC16(dst, src) \
    asm volatile("cp.async.ca.shared.global [%0], [%1], 16;" :: "r"(dst), "l"(src) : "memory")
#define CP_COMMIT() asm volatile("cp.async.commit_group;" ::: "memory")
#define CP_WAIT(n)  asm volatile("cp.async.wait_group %0;" :: "n"(n) : "memory")

__device__ __forceinline__ void gsync(unsigned* bar, unsigned target) {
    __syncthreads();
    if (threadIdx.x == 0) {
        __threadfence();
        atomicAdd(bar, 1u);
        unsigned v;
        do {
            asm volatile("ld.acquire.gpu.global.u32 %0, [%1];" : "=r"(v) : "l"(bar));
        } while (v < target);
    }
    __syncthreads();
}

// ---------------- prep ----------------
__global__ void prep_kernel(const int* __restrict__ xs, const int* __restrict__ as,
                            const float* __restrict__ encWi, const float* __restrict__ encWh,
                            const float* __restrict__ encB,
                            const float* __restrict__ decWi, const float* __restrict__ decWh,
                            const float* __restrict__ decB,
                            const float* __restrict__ w1, const float* __restrict__ w2) {
    int stride = gridDim.x * blockDim.x;
    const int TOT = cH4 * KCAT;
    for (int idx = blockIdx.x * blockDim.x + threadIdx.x; idx < TOT; idx += stride) {
        {   // catW: new row 4j+g <- source row g*512+j
            int nr = idx >> 10, k = idx & 1023;
            int j = nr >> 2, g = nr & 3;
            int r = g * cH + j;
            float v = (k < cH) ? decWi[r * (cH + 1) + k]
                               : decWh[r * cH + (k - cH)];
            g_catW[idx] = __float2bfloat16_rn(v);
        }
        if (idx < cH4 * cH) {
            int nr = idx >> 9, k = idx & 511;
            int j = nr >> 2, g = nr & 3;
            g_Whx[idx] = __float2bfloat16_rn(encWh[(g * cH + j) * cH + k]);
        }
        if (idx < cH * cH) {
            g_w1b[idx] = __float2bfloat16_rn(w1[idx]);
            g_w2b[idx] = __float2bfloat16_rn(w2[idx]);
        }
        if (idx < cH4) {
            int j = idx >> 2, g = idx & 3;
            g_Wie[idx] = encWi[g * cH + j];
            g_Wid[idx] = decWi[(g * cH + j) * (cH + 1) + cH];
            g_be[idx]  = encB[g * cH + j];
            g_bd[idx]  = decB[g * cH + j];
        }
        if (idx < cB * cH) { g_hb[0][idx] = __float2bfloat16_rn(0.0f); g_c[idx] = 0.0f; }
        if (idx < cL * cB) {
            int tt = idx / cB, bb = idx - tt * cB;
            g_decin[idx] = (tt == 0) ? 0.0f
                         : (float)xs[bb * cL + as[bb * cL + tt - 1]];
        }
        if (idx == 0) g_barE = 0u;
    }
}

// ---------------- 4-warp MMA on one 64x64x32 chunk ----------------
__device__ __forceinline__ void mma4_chunk(const bf16* aS, const bf16* wS,
                                           float (*acc)[4], int w, int g4, int q2) {
#pragma unroll
    for (int ks = 0; ks < 32; ks += 16) {
        uint32_t a[4];
        const bf16* ar = aS + (16 * w + g4) * 40 + ks + q2;
        a[0] = *(const uint32_t*)ar;
        a[1] = *(const uint32_t*)(ar + 8 * 40);
        a[2] = *(const uint32_t*)(ar + 8);
        a[3] = *(const uint32_t*)(ar + 8 * 40 + 8);
#pragma unroll
        for (int nt = 0; nt < 8; nt++) {
            uint32_t b[2];
            const bf16* br = wS + (8 * nt + g4) * 40 + ks + q2;
            b[0] = *(const uint32_t*)br;
            b[1] = *(const uint32_t*)(br + 8);
            mma_bf16(acc[nt], a, b);
        }
    }
}

// ---------------- persistent encoder: 128 LSTM steps, W resident in smem ----
__global__ __launch_bounds__(128)
void enc_persist(const int* __restrict__ xs) {
    extern __shared__ __align__(16) bf16 smem[];
    bf16* sWres = smem;              // 16 chunks x 64 x 40 (80 KB, resident)
    bf16* sA    = smem + 16 * 2560;  // 4 stages  x 64 x 40 (20 KB)
    int tid = threadIdx.x, w = tid >> 5, lane = tid & 31;
    int g4 = lane >> 2, q2 = (lane & 3) * 2;
    int nb = blockIdx.x & 31, mb = blockIdx.x >> 5;
    int m0 = mb * 64, n0 = nb * 64;
    uint32_t sW_u = smem_u32(sWres), sA_u = smem_u32(sA);
    int lr = tid >> 2, lc8 = (tid & 3) * 8;

    const bf16* Wg = g_Whx + (size_t)n0 * cH;
#pragma unroll
    for (int c = 0; c < 16; c++)
#pragma unroll
        for (int it = 0; it < 2; it++) {
            int r = lr + 32 * it;
            CP_ASYNC16(sW_u + (uint32_t)(c * 2560 + r * 40 + lc8) * 2,
                       Wg + (size_t)r * cH + c * 32 + lc8);
        }
    CP_COMMIT(); CP_WAIT(0);
    __syncthreads();

    unsigned target = 0;
    int cur = 0;
    for (int t = 0; t < cL; t++) {
        const bf16* Ab = g_hb[cur] + (size_t)m0 * cH;
        bf16* hout = g_hb[cur ^ 1];
        float acc[8][4];
#pragma unroll
        for (int i = 0; i < 8; i++)
#pragma unroll
            for (int j = 0; j < 4; j++) acc[i][j] = 0.0f;

#pragma unroll
        for (int pc = 0; pc < 3; pc++) {
#pragma unroll
            for (int it = 0; it < 2; it++) {
                int r = lr + 32 * it;
                CP_ASYNC16(sA_u + (uint32_t)(pc * 2560 + r * 40 + lc8) * 2,
                           Ab + (size_t)r * cH + pc * 32 + lc8);
            }
            CP_COMMIT();
        }
        for (int i = 0; i < 16; i++) {
            int rem = 15 - i;
            if (rem >= 2) { CP_WAIT(2); } else if (rem == 1) { CP_WAIT(1); } else { CP_WAIT(0); }
            __syncthreads();
            int nxt = i + 3;
            if (nxt < 16) {
                int st = nxt & 3;
#pragma unroll
                for (int it = 0; it < 2; it++) {
                    int r = lr + 32 * it;
                    CP_ASYNC16(sA_u + (uint32_t)(st * 2560 + r * 40 + lc8) * 2,
                               Ab + (size_t)r * cH + nxt * 32 + lc8);
                }
                CP_COMMIT();
            }
            mma4_chunk(sA + (i & 3) * 2560, sWres + i * 2560, acc, w, g4, q2);
        }
        __syncthreads();

        float* sZ = (float*)sA;   // 64 x 65 fp32 = 16.6 KB
        int zr = 16 * w + g4;
#pragma unroll
        for (int nt = 0; nt < 8; nt++) {
            int col = 8 * nt + q2;
            sZ[zr * 65 + col]           = acc[nt][0];
            sZ[zr * 65 + col + 1]       = acc[nt][1];
            sZ[(zr + 8) * 65 + col]     = acc[nt][2];
            sZ[(zr + 8) * 65 + col + 1] = acc[nt][3];
        }
        __syncthreads();
#pragma unroll
        for (int i2 = 0; i2 < 8; i2++) {
            int it = tid + i2 * 128;
            int row = it >> 4, u = it & 15;
            int b = m0 + row;
            int U = (n0 >> 2) + u;
            const float* zq = sZ + row * 65 + 4 * u;
            float zi = zq[0] + g_be[4 * U + 0];
            float zf = zq[1] + g_be[4 * U + 1];
            float zg = zq[2] + g_be[4 * U + 2];
            float zo = zq[3] + g_be[4 * U + 3];
            float xt = (float)xs[b * cL + t];
            zi = fmaf(xt, g_Wie[4 * U + 0], zi);
            zf = fmaf(xt, g_Wie[4 * U + 1], zf);
            zg = fmaf(xt, g_Wie[4 * U + 2], zg);
            zo = fmaf(xt, g_Wie[4 * U + 3], zo);
            float cold = g_c[b * cH + U];
            float cn = acc_sig(zf) * cold + acc_sig(zi) * acc_tanh(zg);
            float hn = acc_sig(zo) * acc_tanh(cn);
            g_c[b * cH + U] = cn;
            bf16 hr = __float2bfloat16_rn(hn);
            hout[b * cH + U] = hr;
            g_enc_outb[(size_t)(b * cL + t) * cH + U] = hr;
        }
        cur ^= 1;
        target += NBLK;
        gsync(&g_barE, target);
    }
}

// ---------------- one-shot GEMM: enc_w1 = enc_out @ w1^T (bf16 out) ----------------
__global__ __launch_bounds__(128)
void gemm_w1() {
    __shared__ __align__(16) bf16 s[8 * 2560];
    bf16* sA = s;
    bf16* sW = s + 4 * 2560;
    int tid = threadIdx.x, w = tid >> 5, lane = tid & 31;
    int g4 = lane >> 2, q2 = (lane & 3) * 2;
    int n0 = blockIdx.x * 64, m0 = blockIdx.y * 64;
    uint32_t sA_u = smem_u32(sA), sW_u = smem_u32(sW);
    int lr = tid >> 2, lc8 = (tid & 3) * 8;
    const bf16* Ab = g_enc_outb + (size_t)m0 * cH;
    const bf16* Wb = g_w1b + (size_t)n0 * cH;

    float acc[8][4];
#pragma unroll
    for (int i = 0; i < 8; i++)
#pragma unroll
        for (int j = 0; j < 4; j++) acc[i][j] = 0.0f;

#pragma unroll
    for (int pc = 0; pc < 3; pc++) {
#pragma unroll
        for (int it = 0; it < 2; it++) {
            int r = lr + 32 * it;
            CP_ASYNC16(sA_u + (uint32_t)(pc * 2560 + r * 40 + lc8) * 2,
                       Ab + (size_t)r * cH + pc * 32 + lc8);
            CP_ASYNC16(sW_u + (uint32_t)(pc * 2560 + r * 40 + lc8) * 2,
                       Wb + (size_t)r * cH + pc * 32 + lc8);
        }
        CP_COMMIT();
    }
    for (int i = 0; i < 16; i++) {
        int rem = 15 - i;
        if (rem >= 2) { CP_WAIT(2); } else if (rem == 1) { CP_WAIT(1); } else { CP_WAIT(0); }
        __syncthreads();
        int nxt = i + 3;
        if (nxt < 16) {
            int st = nxt & 3;
#pragma unroll
            for (int it = 0; it < 2; it++) {
                int r = lr + 32 * it;
                CP_ASYNC16(sA_u + (uint32_t)(st * 2560 + r * 40 + lc8) * 2,
                           Ab + (size_t)r * cH + nxt * 32 + lc8);
                CP_ASYNC16(sW_u + (uint32_t)(st * 2560 + r * 40 + lc8) * 2,
                           Wb + (size_t)r * cH + nxt * 32 + lc8);
            }
            CP_COMMIT();
        }
        mma4_chunk(sA + (i & 3) * 2560, sW + (i & 3) * 2560, acc, w, g4, q2);
    }
    __syncthreads();

    int mrow = m0 + 16 * w + g4;
#pragma unroll
    for (int nt = 0; nt < 8; nt++) {
        int col = n0 + 8 * nt + q2;
        __nv_bfloat162 p0, p1;
        p0.x = __float2bfloat16_rn(acc[nt][0]); p0.y = __float2bfloat16_rn(acc[nt][1]);
        p1.x = __float2bfloat16_rn(acc[nt][2]); p1.y = __float2bfloat16_rn(acc[nt][3]);
        *(__nv_bfloat162*)&g_enc_w1b[(size_t)mrow * cH + col]       = p0;
        *(__nv_bfloat162*)&g_enc_w1b[(size_t)(mrow + 8) * cH + col] = p1;
    }
}

// ---------------- decoder launch-based GEMM ----------------
// mode 0: fp32 store to C.  mode 2: dec LSTM gates (x from g_decin).
constexpr int BM = 64, BN = 64, BK = 32;
constexpr int TSB = 40;
constexpr int STAGES = 4;
constexpr int STE = BM * TSB;

__global__ __launch_bounds__(128)
void gemm_mma(const bf16* __restrict__ A, const bf16* __restrict__ W,
              float* __restrict__ C, const float* __restrict__ bias4,
              bf16* __restrict__ h_out,
              int M, int N, int K, int mode, int t) {
    __shared__ __align__(16) bf16 sA[STAGES * STE];
    __shared__ __align__(16) bf16 sW[STAGES * STE];

    int tid = threadIdx.x;
    int w = tid >> 5, lane = tid & 31;
    int g4 = lane >> 2, q2 = (lane & 3) * 2;
    int n0 = blockIdx.x * BN, m0 = blockIdx.y * BM;

    uint32_t sA_u = smem_u32(sA);
    uint32_t sW_u = smem_u32(sW);
    const bf16* Ab = A + (size_t)m0 * K;
    const bf16* Wb = W + (size_t)n0 * K;

    int lr = tid >> 2, lc8 = (tid & 3) * 8;

    float acc[8][4];
#pragma unroll
    for (int i = 0; i < 8; i++)
#pragma unroll
        for (int j = 0; j < 4; j++) acc[i][j] = 0.0f;

    const int NC = K / BK;

#pragma unroll
    for (int pc = 0; pc < STAGES - 1; pc++) {
        int koff = pc * BK;
#pragma unroll
        for (int it = 0; it < 2; it++) {
            int r = lr + it * 32;
            CP_ASYNC16(sA_u + (uint32_t)(pc * STE + r * TSB + lc8) * 2,
                       Ab + (size_t)r * K + koff + lc8);
            CP_ASYNC16(sW_u + (uint32_t)(pc * STE + r * TSB + lc8) * 2,
                       Wb + (size_t)r * K + koff + lc8);
        }
        CP_COMMIT();
    }

    for (int i = 0; i < NC; i++) {
        int rem = NC - 1 - i;
        if (rem >= STAGES - 2) { CP_WAIT(STAGES - 2); }
        else if (rem == 2)     { CP_WAIT(2); }
        else if (rem == 1)     { CP_WAIT(1); }
        else                   { CP_WAIT(0); }
        __syncthreads();

        int nxt = i + STAGES - 1;
        if (nxt < NC) {
            int st = nxt % STAGES;
            int koff = nxt * BK;
#pragma unroll
            for (int it = 0; it < 2; it++) {
                int r = lr + it * 32;
                CP_ASYNC16(sA_u + (uint32_t)(st * STE + r * TSB + lc8) * 2,
                           Ab + (size_t)r * K + koff + lc8);
                CP_ASYNC16(sW_u + (uint32_t)(st * STE + r * TSB + lc8) * 2,
                           Wb + (size_t)r * K + koff + lc8);
            }
            CP_COMMIT();
        }

        mma4_chunk(sA + (i % STAGES) * STE, sW + (i % STAGES) * STE, acc, w, g4, q2);
    }
    __syncthreads();

    if (mode == 0) {
        int mrow = m0 + 16 * w + g4;
#pragma unroll
        for (int nt = 0; nt < 8; nt++) {
            int col = n0 + 8 * nt + q2;
            C[(size_t)mrow * N + col]           = acc[nt][0];
            C[(size_t)mrow * N + col + 1]       = acc[nt][1];
            C[(size_t)(mrow + 8) * N + col]     = acc[nt][2];
            C[(size_t)(mrow + 8) * N + col + 1] = acc[nt][3];
        }
        return;
    }

    // gate epilogue (decoder)
    float* sZ = (float*)sA;
    int zr = 16 * w + g4;
#pragma unroll
    for (int nt = 0; nt < 8; nt++) {
        int col = 8 * nt + q2;
        sZ[zr * 65 + col]           = acc[nt][0];
        sZ[zr * 65 + col + 1]       = acc[nt][1];
        sZ[(zr + 8) * 65 + col]     = acc[nt][2];
        sZ[(zr + 8) * 65 + col + 1] = acc[nt][3];
    }
    __syncthreads();

#pragma unroll
    for (int i = 0; i < 8; i++) {
        int it = tid + i * 128;
        int row = it >> 4, u = it & 15;
        int b = m0 + row;
        int U = (n0 >> 2) + u;
        const float* zq = sZ + row * 65 + 4 * u;
        float zi = zq[0] + bias4[4 * U + 0];
        float zf = zq[1] + bias4[4 * U + 1];
        float zg = zq[2] + bias4[4 * U + 2];
        float zo = zq[3] + bias4[4 * U + 3];
        float xt = g_decin[t * cB + b];
        zi = fmaf(xt, g_Wid[4 * U + 0], zi);
        zf = fmaf(xt, g_Wid[4 * U + 1], zf);
        zg = fmaf(xt, g_Wid[4 * U + 2], zg);
        zo = fmaf(xt, g_Wid[4 * U + 3], zo);
        float cold = g_c[b * cH + U];
        float cn = acc_sig(zf) * cold + acc_sig(zi) * acc_tanh(zg);
        float hn = acc_sig(zo) * acc_tanh(cn);
        g_c[b * cH + U] = cn;
        h_out[b * cH + U] = __float2bfloat16_rn(hn);
    }
}

// ---------------- fused attention ----------------
__global__ __launch_bounds__(512)
void attn_fused(const float* __restrict__ vt_p, int t, float* __restrict__ out,
                const bf16* __restrict__ hb) {
    __shared__ float qs[cH];
    __shared__ float vts[cH];
    __shared__ float sc[cL];
    __shared__ float ajs[cL];
    __shared__ float redm[16];
    __shared__ float reds[16];

    int b = blockIdx.x;
    int tid = threadIdx.x;
    int warp = tid >> 5, lane = tid & 31;

    for (int i = tid; i < cH; i += 512) {
        qs[i]  = g_q[b * cH + i];
        vts[i] = vt_p[i];
    }
    __syncthreads();

    for (int l = warp; l < cL; l += 16) {
        const __nv_bfloat162* row =
            (const __nv_bfloat162*)(g_enc_w1b + (size_t)(b * cL + l) * cH);
        float s = 0.0f;
#pragma unroll 4
        for (int j = lane; j < cH / 2; j += 32) {
            __nv_bfloat162 p = row[j];
            float2 qv = *(const float2*)(qs + 2 * j);
            float2 vv = *(const float2*)(vts + 2 * j);
            s = fmaf(vv.x, mufu_tanh(__bfloat162float(p.x) + qv.x), s);
            s = fmaf(vv.y, mufu_tanh(__bfloat162float(p.y) + qv.y), s);
        }
#pragma unroll
        for (int o = 16; o > 0; o >>= 1) s += __shfl_xor_sync(0xffffffffu, s, o);
        if (lane == 0) sc[l] = s;
    }
    __syncthreads();

    float sval = (tid < cL) ? sc[tid] : -3.0e38f;
    float m = sval;
#pragma unroll
    for (int o = 16; o > 0; o >>= 1) m = fmaxf(m, __shfl_xor_sync(0xffffffffu, m, o));
    if (lane == 0) redm[warp] = m;
    __syncthreads();
    if (tid < 16) {
        float mm = redm[tid];
#pragma unroll
        for (int o = 8; o > 0; o >>= 1) mm = fmaxf(mm, __shfl_xor_sync(0x0000ffffu, mm, o));
        if (tid == 0) redm[0] = mm;
    }
    __syncthreads();
    float mx = redm[0];

    float e = (tid < cL) ? __expf(sval - mx) : 0.0f;
    float ss = e;
#pragma unroll
    for (int o = 16; o > 0; o >>= 1) ss += __shfl_xor_sync(0xffffffffu, ss, o);
    if (lane == 0) reds[warp] = ss;
    __syncthreads();
    if (tid < 16) {
        float s2 = reds[tid];
#pragma unroll
        for (int o = 8; o > 0; o >>= 1) s2 += __shfl_xor_sync(0x0000ffffu, s2, o);
        if (tid == 0) reds[0] = s2;
    }
    __syncthreads();
    float tot = reds[0];

    if (tid < cL) {
        out[((size_t)b * cL + t) * cL + tid] = sval - mx - __logf(tot);
        ajs[tid] = __fdividef(e, tot);
    }
    __syncthreads();

    float acc = 0.0f;
    const bf16* eo = g_enc_outb + (size_t)b * cL * cH + tid;
#pragma unroll 8
    for (int l = 0; l < cL; l++)
        acc = fmaf(ajs[l], __bfloat162float(eo[(size_t)l * cH]), acc);

    g_xcatb[b * KCAT + tid]      = __float2bfloat16_rn(acc);
    g_xcatb[b * KCAT + cH + tid] = hb[b * cH + tid];
}

// ---------------- host orchestration ----------------
extern "C" void kernel_launch(void* const* d_in, const int* in_sizes, int n_in,
                              void* d_out, int out_size) {
    const int*   xs      = (const int*)d_in[0];
    const int*   argsort = (const int*)d_in[2];
    const float* enc_Wi  = (const float*)d_in[3];
    const float* enc_Wh  = (const float*)d_in[4];
    const float* enc_b   = (const float*)d_in[5];
    const float* dec_Wi  = (const float*)d_in[6];
    const float* dec_Wh  = (const float*)d_in[7];
    const float* dec_b   = (const float*)d_in[8];
    const float* w1      = (const float*)d_in[9];
    const float* w2      = (const float*)d_in[10];
    const float* vt      = (const float*)d_in[11];
    float*       out     = (float*)d_out;

    bf16 *ph0, *ph1, *pxcat, *pcatW, *pw2b;
    float *pq, *pbd;
    cudaGetSymbolAddress((void**)&ph0,   g_hb);
    ph1 = ph0 + cB * cH;
    cudaGetSymbolAddress((void**)&pq,    g_q);
    cudaGetSymbolAddress((void**)&pxcat, g_xcatb);
    cudaGetSymbolAddress((void**)&pcatW, g_catW);
    cudaGetSymbolAddress((void**)&pw2b,  g_w2b);
    cudaGetSymbolAddress((void**)&pbd,   g_bd);

    // one-time setup (kept out of graph capture, matching the R12-proven pattern)
    static bool attr_done = false;
    if (!attr_done) {
        cudaFuncSetAttribute(enc_persist, cudaFuncAttributeMaxDynamicSharedMemorySize, 102400);
        attr_done = true;
    }

    prep_kernel<<<2080, 1024>>>(xs, argsort, enc_Wi, enc_Wh, enc_b,
                                dec_Wi, dec_Wh, dec_b, w1, w2);

    // persistent encoder: all 128 steps in one launch
    enc_persist<<<NBLK, 128, 102400>>>(xs);

    // enc_w1 = enc_out @ w1^T
    gemm_w1<<<dim3(cH / 64, (cB * cL) / 64), 128>>>();

    // decoder: launch-based
    bf16* hb[2] = {ph0, ph1};
    int cur = 0;
    for (int t = 0; t < cL; t++) {
        gemm_mma<<<dim3(cH / BN, cB / BM), 128>>>(
            hb[cur], pw2b, pq, nullptr, nullptr,
            cB, cH, cH, 0, 0);
        attn_fused<<<cB, 512>>>(vt, t, out, hb[cur]);
        gemm_mma<<<dim3(cH4 / BN, cB / BM), 128>>>(
            pxcat, pcatW, nullptr, pbd, hb[cur ^ 1],
            cB, cH4, KCAT, 2, t);
        cur ^= 1;
    }
}

// round 16
// speedup vs baseline: 1.5807x; 1.0916x over previous
#include <cuda_runtime.h>
#include <cuda_bf16.h>
#include <math.h>
#include <cstdint>

constexpr int cB  = 256;
constexpr int cL  = 128;
constexpr int cH  = 512;
constexpr int cH4 = 2048;
constexpr int KCAT = 1024;
constexpr int NBLK = 128;      // persistent encoder grid (<= 148 SMs)

typedef __nv_bfloat16 bf16;

__device__ __align__(16) bf16  g_hb[2][cB * cH];
__device__ float g_c[cB * cH];
__device__ float g_q[cB * cH];
__device__ __align__(16) bf16  g_enc_outb[(size_t)cB * cL * cH];
__device__ __align__(16) bf16  g_enc_w1b[(size_t)cB * cL * cH];
__device__ __align__(16) bf16  g_xcatb[cB * KCAT];
__device__ __align__(16) bf16  g_Whx[(size_t)cH4 * cH];
__device__ __align__(16) bf16  g_catW[(size_t)cH4 * KCAT];
__device__ __align__(16) bf16  g_w1b[(size_t)cH * cH];
__device__ __align__(16) bf16  g_w2b[(size_t)cH * cH];
__device__ float g_Wie[cH4];
__device__ float g_Wid[cH4];
__device__ float g_be[cH4];
__device__ float g_bd[cH4];
__device__ float g_decin[cL * cB];
__device__ unsigned g_barE;

// ---------------- math / PTX helpers ----------------
__device__ __forceinline__ float acc_tanh(float x) {
    float a = fabsf(x);
    float e = __expf(-2.0f * a);
    float r = __fdividef(1.0f - e, 1.0f + e);
    return copysignf(r, x);
}
__device__ __forceinline__ float acc_sig(float x) {
    return __fdividef(1.0f, 1.0f + __expf(-x));
}
__device__ __forceinline__ float mufu_tanh(float x) {
    float y; asm("tanh.approx.f32 %0, %1;" : "=f"(y) : "f"(x)); return y;
}
__device__ __forceinline__ void mma_bf16(float* d, const uint32_t* a, const uint32_t* b) {
    asm volatile("mma.sync.aligned.m16n8k16.row.col.f32.bf16.bf16.f32 "
                 "{%0,%1,%2,%3}, {%4,%5,%6,%7}, {%8,%9}, {%0,%1,%2,%3};"
                 : "+f"(d[0]), "+f"(d[1]), "+f"(d[2]), "+f"(d[3])
                 : "r"(a[0]), "r"(a[1]), "r"(a[2]), "r"(a[3]), "r"(b[0]), "r"(b[1]));
}
__device__ __forceinline__ uint32_t smem_u32(const void* p) {
    uint32_t a;
    asm("{ .reg .u64 t; cvta.to.shared.u64 t, %1; cvt.u32.u64 %0, t; }" : "=r"(a) : "l"(p));
    return a;
}
#define CP_ASYNC16(dst, src) \
    asm volatile("cp.async.ca.shared.global [%0], [%1], 16;" :: "r"(dst), "l"(src) : "memory")
#define CP_COMMIT() asm volatile("cp.async.commit_group;" ::: "memory")
#define CP_WAIT(n)  asm volatile("cp.async.wait_group %0;" :: "n"(n) : "memory")

__device__ __forceinline__ void gsync(unsigned* bar, unsigned target) {
    __syncthreads();
    if (threadIdx.x == 0) {
        __threadfence();
        atomicAdd(bar, 1u);
        unsigned v;
        do {
            asm volatile("ld.acquire.gpu.global.u32 %0, [%1];" : "=r"(v) : "l"(bar));
        } while (v < target);
    }
    __syncthreads();
}

// ---------------- prep ----------------
__global__ void prep_kernel(const int* __restrict__ xs, const int* __restrict__ as,
                            const float* __restrict__ encWi, const float* __restrict__ encWh,
                            const float* __restrict__ encB,
                            const float* __restrict__ decWi, const float* __restrict__ decWh,
                            const float* __restrict__ decB,
                            const float* __restrict__ w1, const float* __restrict__ w2) {
    int stride = gridDim.x * blockDim.x;
    const int TOT = cH4 * KCAT;
    for (int idx = blockIdx.x * blockDim.x + threadIdx.x; idx < TOT; idx += stride) {
        {   // catW: new row 4j+g <- source row g*512+j
            int nr = idx >> 10, k = idx & 1023;
            int j = nr >> 2, g = nr & 3;
            int r = g * cH + j;
            float v = (k < cH) ? decWi[r * (cH + 1) + k]
                               : decWh[r * cH + (k - cH)];
            g_catW[idx] = __float2bfloat16_rn(v);
        }
        if (idx < cH4 * cH) {
            int nr = idx >> 9, k = idx & 511;
            int j = nr >> 2, g = nr & 3;
            g_Whx[idx] = __float2bfloat16_rn(encWh[(g * cH + j) * cH + k]);
        }
        if (idx < cH * cH) {
            g_w1b[idx] = __float2bfloat16_rn(w1[idx]);
            g_w2b[idx] = __float2bfloat16_rn(w2[idx]);
        }
        if (idx < cH4) {
            int j = idx >> 2, g = idx & 3;
            g_Wie[idx] = encWi[g * cH + j];
            g_Wid[idx] = decWi[(g * cH + j) * (cH + 1) + cH];
            g_be[idx]  = encB[g * cH + j];
            g_bd[idx]  = decB[g * cH + j];
        }
        if (idx < cB * cH) { g_hb[0][idx] = __float2bfloat16_rn(0.0f); g_c[idx] = 0.0f; }
        if (idx < cL * cB) {
            int tt = idx / cB, bb = idx - tt * cB;
            g_decin[idx] = (tt == 0) ? 0.0f
                         : (float)xs[bb * cL + as[bb * cL + tt - 1]];
        }
        if (idx == 0) g_barE = 0u;
    }
}

// ---------------- 8-warp MMA on one 64x64x32 chunk (warps 2m x 4n, warp tile 32x16) --
__device__ __forceinline__ void mma8_chunk(const bf16* aS, const bf16* wS,
                                           float acc[2][2][4],
                                           int wm, int wn, int g4, int q2) {
#pragma unroll
    for (int ks = 0; ks < 32; ks += 16) {
        uint32_t a0[4], a1[4];
        const bf16* ar = aS + (32 * wm + g4) * 40 + ks + q2;
        a0[0] = *(const uint32_t*)ar;
        a0[1] = *(const uint32_t*)(ar + 8 * 40);
        a0[2] = *(const uint32_t*)(ar + 8);
        a0[3] = *(const uint32_t*)(ar + 8 * 40 + 8);
        const bf16* ar1 = ar + 16 * 40;
        a1[0] = *(const uint32_t*)ar1;
        a1[1] = *(const uint32_t*)(ar1 + 8 * 40);
        a1[2] = *(const uint32_t*)(ar1 + 8);
        a1[3] = *(const uint32_t*)(ar1 + 8 * 40 + 8);
#pragma unroll
        for (int nt = 0; nt < 2; nt++) {
            uint32_t b[2];
            const bf16* br = wS + (16 * wn + 8 * nt + g4) * 40 + ks + q2;
            b[0] = *(const uint32_t*)br;
            b[1] = *(const uint32_t*)(br + 8);
            mma_bf16(acc[0][nt], a0, b);
            mma_bf16(acc[1][nt], a1, b);
        }
    }
}

// ---------------- persistent encoder: 128 LSTM steps, W resident, 8 warps ----
__global__ __launch_bounds__(256)
void enc_persist(const int* __restrict__ xs) {
    extern __shared__ __align__(16) bf16 smem[];
    bf16* sWres = smem;              // 16 chunks x 64 x 40 (80 KB, resident)
    bf16* sA    = smem + 16 * 2560;  // 4 stages  x 64 x 40 (20 KB)
    int tid = threadIdx.x, lane = tid & 31, w8 = tid >> 5;
    int wm = w8 >> 2, wn = w8 & 3;
    int g4 = lane >> 2, q2 = (lane & 3) * 2;
    int nb = blockIdx.x & 31, mb = blockIdx.x >> 5;
    int m0 = mb * 64, n0 = nb * 64;
    uint32_t sW_u = smem_u32(sWres), sA_u = smem_u32(sA);
    int lr = tid >> 2, lc8 = (tid & 3) * 8;   // 64 rows x 4 x 16B: 1 slot/thread

    const bf16* Wg = g_Whx + (size_t)n0 * cH;
#pragma unroll
    for (int c = 0; c < 16; c++)
        CP_ASYNC16(sW_u + (uint32_t)(c * 2560 + lr * 40 + lc8) * 2,
                   Wg + (size_t)lr * cH + c * 32 + lc8);
    CP_COMMIT(); CP_WAIT(0);
    __syncthreads();

    unsigned target = 0;
    int cur = 0;
    for (int t = 0; t < cL; t++) {
        const bf16* Ab = g_hb[cur] + (size_t)m0 * cH;
        bf16* hout = g_hb[cur ^ 1];
        float acc[2][2][4];
#pragma unroll
        for (int i = 0; i < 2; i++)
#pragma unroll
            for (int j = 0; j < 2; j++)
#pragma unroll
                for (int k = 0; k < 4; k++) acc[i][j][k] = 0.0f;

#pragma unroll
        for (int pc = 0; pc < 3; pc++) {
            CP_ASYNC16(sA_u + (uint32_t)(pc * 2560 + lr * 40 + lc8) * 2,
                       Ab + (size_t)lr * cH + pc * 32 + lc8);
            CP_COMMIT();
        }
        for (int i = 0; i < 16; i++) {
            int rem = 15 - i;
            if (rem >= 2) { CP_WAIT(2); } else if (rem == 1) { CP_WAIT(1); } else { CP_WAIT(0); }
            __syncthreads();
            int nxt = i + 3;
            if (nxt < 16) {
                int st = nxt & 3;
                CP_ASYNC16(sA_u + (uint32_t)(st * 2560 + lr * 40 + lc8) * 2,
                           Ab + (size_t)lr * cH + nxt * 32 + lc8);
                CP_COMMIT();
            }
            mma8_chunk(sA + (i & 3) * 2560, sWres + i * 2560, acc, wm, wn, g4, q2);
        }
        __syncthreads();

        float* sZ = (float*)sA;   // 64 x 65 fp32 = 16.6 KB <= 20 KB
#pragma unroll
        for (int i = 0; i < 2; i++)
#pragma unroll
            for (int nt = 0; nt < 2; nt++) {
                int r = 32 * wm + 16 * i + g4;
                int c = 16 * wn + 8 * nt + q2;
                sZ[r * 65 + c]           = acc[i][nt][0];
                sZ[r * 65 + c + 1]       = acc[i][nt][1];
                sZ[(r + 8) * 65 + c]     = acc[i][nt][2];
                sZ[(r + 8) * 65 + c + 1] = acc[i][nt][3];
            }
        __syncthreads();
#pragma unroll
        for (int i2 = 0; i2 < 4; i2++) {
            int it = tid + i2 * 256;              // 1024 items: 64 rows x 16 units
            int row = it >> 4, u = it & 15;
            int b = m0 + row;
            int U = (n0 >> 2) + u;
            const float* zq = sZ + row * 65 + 4 * u;
            float zi = zq[0] + g_be[4 * U + 0];
            float zf = zq[1] + g_be[4 * U + 1];
            float zg = zq[2] + g_be[4 * U + 2];
            float zo = zq[3] + g_be[4 * U + 3];
            float xt = (float)xs[b * cL + t];
            zi = fmaf(xt, g_Wie[4 * U + 0], zi);
            zf = fmaf(xt, g_Wie[4 * U + 1], zf);
            zg = fmaf(xt, g_Wie[4 * U + 2], zg);
            zo = fmaf(xt, g_Wie[4 * U + 3], zo);
            float cold = g_c[b * cH + U];
            float cn = acc_sig(zf) * cold + acc_sig(zi) * acc_tanh(zg);
            float hn = acc_sig(zo) * acc_tanh(cn);
            g_c[b * cH + U] = cn;
            bf16 hr = __float2bfloat16_rn(hn);
            hout[b * cH + U] = hr;
            g_enc_outb[(size_t)(b * cL + t) * cH + U] = hr;
        }
        cur ^= 1;
        target += NBLK;
        gsync(&g_barE, target);
    }
}

// ---------------- one-shot GEMM: enc_w1 = enc_out @ w1^T (bf16 out, 4-warp) -------
__device__ __forceinline__ void mma4_chunk(const bf16* aS, const bf16* wS,
                                           float (*acc)[4], int w, int g4, int q2) {
#pragma unroll
    for (int ks = 0; ks < 32; ks += 16) {
        uint32_t a[4];
        const bf16* ar = aS + (16 * w + g4) * 40 + ks + q2;
        a[0] = *(const uint32_t*)ar;
        a[1] = *(const uint32_t*)(ar + 8 * 40);
        a[2] = *(const uint32_t*)(ar + 8);
        a[3] = *(const uint32_t*)(ar + 8 * 40 + 8);
#pragma unroll
        for (int nt = 0; nt < 8; nt++) {
            uint32_t b[2];
            const bf16* br = wS + (8 * nt + g4) * 40 + ks + q2;
            b[0] = *(const uint32_t*)br;
            b[1] = *(const uint32_t*)(br + 8);
            mma_bf16(acc[nt], a, b);
        }
    }
}

__global__ __launch_bounds__(128)
void gemm_w1() {
    __shared__ __align__(16) bf16 s[8 * 2560];
    bf16* sA = s;
    bf16* sW = s + 4 * 2560;
    int tid = threadIdx.x, w = tid >> 5, lane = tid & 31;
    int g4 = lane >> 2, q2 = (lane & 3) * 2;
    int n0 = blockIdx.x * 64, m0 = blockIdx.y * 64;
    uint32_t sA_u = smem_u32(sA), sW_u = smem_u32(sW);
    int lr = tid >> 2, lc8 = (tid & 3) * 8;
    const bf16* Ab = g_enc_outb + (size_t)m0 * cH;
    const bf16* Wb = g_w1b + (size_t)n0 * cH;

    float acc[8][4];
#pragma unroll
    for (int i = 0; i < 8; i++)
#pragma unroll
        for (int j = 0; j < 4; j++) acc[i][j] = 0.0f;

#pragma unroll
    for (int pc = 0; pc < 3; pc++) {
#pragma unroll
        for (int it = 0; it < 2; it++) {
            int r = lr + 32 * it;
            CP_ASYNC16(sA_u + (uint32_t)(pc * 2560 + r * 40 + lc8) * 2,
                       Ab + (size_t)r * cH + pc * 32 + lc8);
            CP_ASYNC16(sW_u + (uint32_t)(pc * 2560 + r * 40 + lc8) * 2,
                       Wb + (size_t)r * cH + pc * 32 + lc8);
        }
        CP_COMMIT();
    }
    for (int i = 0; i < 16; i++) {
        int rem = 15 - i;
        if (rem >= 2) { CP_WAIT(2); } else if (rem == 1) { CP_WAIT(1); } else { CP_WAIT(0); }
        __syncthreads();
        int nxt = i + 3;
        if (nxt < 16) {
            int st = nxt & 3;
#pragma unroll
            for (int it = 0; it < 2; it++) {
                int r = lr + 32 * it;
                CP_ASYNC16(sA_u + (uint32_t)(st * 2560 + r * 40 + lc8) * 2,
                           Ab + (size_t)r * cH + nxt * 32 + lc8);
                CP_ASYNC16(sW_u + (uint32_t)(st * 2560 + r * 40 + lc8) * 2,
                           Wb + (size_t)r * cH + nxt * 32 + lc8);
            }
            CP_COMMIT();
        }
        mma4_chunk(sA + (i & 3) * 2560, sW + (i & 3) * 2560, acc, w, g4, q2);
    }
    __syncthreads();

    int mrow = m0 + 16 * w + g4;
#pragma unroll
    for (int nt = 0; nt < 8; nt++) {
        int col = n0 + 8 * nt + q2;
        __nv_bfloat162 p0, p1;
        p0.x = __float2bfloat16_rn(acc[nt][0]); p0.y = __float2bfloat16_rn(acc[nt][1]);
        p1.x = __float2bfloat16_rn(acc[nt][2]); p1.y = __float2bfloat16_rn(acc[nt][3]);
        *(__nv_bfloat162*)&g_enc_w1b[(size_t)mrow * cH + col]       = p0;
        *(__nv_bfloat162*)&g_enc_w1b[(size_t)(mrow + 8) * cH + col] = p1;
    }
}

// ---------------- decoder GEMM: 256 threads / 8 warps, 64x64 tile -----------------
// mode 0: fp32 store to C.  mode 2: dec LSTM gates (x from g_decin).
__global__ __launch_bounds__(256)
void dec_gemm(const bf16* __restrict__ A, const bf16* __restrict__ W,
              float* __restrict__ C, const float* __restrict__ bias4,
              bf16* __restrict__ h_out,
              int M, int N, int K, int mode, int t) {
    __shared__ __align__(16) bf16 sA[4 * 2560];
    __shared__ __align__(16) bf16 sW[4 * 2560];

    int tid = threadIdx.x, lane = tid & 31, w8 = tid >> 5;
    int wm = w8 >> 2, wn = w8 & 3;
    int g4 = lane >> 2, q2 = (lane & 3) * 2;
    int n0 = blockIdx.x * 64, m0 = blockIdx.y * 64;

    uint32_t sA_u = smem_u32(sA), sW_u = smem_u32(sW);
    const bf16* Ab = A + (size_t)m0 * K;
    const bf16* Wb = W + (size_t)n0 * K;
    int lr = tid >> 2, lc8 = (tid & 3) * 8;   // 1 slot per thread per operand

    float acc[2][2][4];
#pragma unroll
    for (int i = 0; i < 2; i++)
#pragma unroll
        for (int j = 0; j < 2; j++)
#pragma unroll
            for (int k = 0; k < 4; k++) acc[i][j][k] = 0.0f;

    const int NC = K / 32;

#pragma unroll
    for (int pc = 0; pc < 3; pc++) {
        CP_ASYNC16(sA_u + (uint32_t)(pc * 2560 + lr * 40 + lc8) * 2,
                   Ab + (size_t)lr * K + pc * 32 + lc8);
        CP_ASYNC16(sW_u + (uint32_t)(pc * 2560 + lr * 40 + lc8) * 2,
                   Wb + (size_t)lr * K + pc * 32 + lc8);
        CP_COMMIT();
    }
    for (int i = 0; i < NC; i++) {
        int rem = NC - 1 - i;
        if (rem >= 2) { CP_WAIT(2); } else if (rem == 1) { CP_WAIT(1); } else { CP_WAIT(0); }
        __syncthreads();
        int nxt = i + 3;
        if (nxt < NC) {
            int st = nxt & 3;
            CP_ASYNC16(sA_u + (uint32_t)(st * 2560 + lr * 40 + lc8) * 2,
                       Ab + (size_t)lr * K + nxt * 32 + lc8);
            CP_ASYNC16(sW_u + (uint32_t)(st * 2560 + lr * 40 + lc8) * 2,
                       Wb + (size_t)lr * K + nxt * 32 + lc8);
            CP_COMMIT();
        }
        mma8_chunk(sA + (i & 3) * 2560, sW + (i & 3) * 2560, acc, wm, wn, g4, q2);
    }
    __syncthreads();

    if (mode == 0) {
#pragma unroll
        for (int i = 0; i < 2; i++)
#pragma unroll
            for (int nt = 0; nt < 2; nt++) {
                int r = m0 + 32 * wm + 16 * i + g4;
                int c = n0 + 16 * wn + 8 * nt + q2;
                C[(size_t)r * N + c]           = acc[i][nt][0];
                C[(size_t)r * N + c + 1]       = acc[i][nt][1];
                C[(size_t)(r + 8) * N + c]     = acc[i][nt][2];
                C[(size_t)(r + 8) * N + c + 1] = acc[i][nt][3];
            }
        return;
    }

    // gate epilogue (decoder LSTM)
    float* sZ = (float*)sA;
#pragma unroll
    for (int i = 0; i < 2; i++)
#pragma unroll
        for (int nt = 0; nt < 2; nt++) {
            int r = 32 * wm + 16 * i + g4;
            int c = 16 * wn + 8 * nt + q2;
            sZ[r * 65 + c]           = acc[i][nt][0];
            sZ[r * 65 + c + 1]       = acc[i][nt][1];
            sZ[(r + 8) * 65 + c]     = acc[i][nt][2];
            sZ[(r + 8) * 65 + c + 1] = acc[i][nt][3];
        }
    __syncthreads();

#pragma unroll
    for (int i2 = 0; i2 < 4; i2++) {
        int it = tid + i2 * 256;                 // 1024 items: 64 rows x 16 units
        int row = it >> 4, u = it & 15;
        int b = m0 + row;
        int U = (n0 >> 2) + u;
        const float* zq = sZ + row * 65 + 4 * u;
        float zi = zq[0] + bias4[4 * U + 0];
        float zf = zq[1] + bias4[4 * U + 1];
        float zg = zq[2] + bias4[4 * U + 2];
        float zo = zq[3] + bias4[4 * U + 3];
        float xt = g_decin[t * cB + b];
        zi = fmaf(xt, g_Wid[4 * U + 0], zi);
        zf = fmaf(xt, g_Wid[4 * U + 1], zf);
        zg = fmaf(xt, g_Wid[4 * U + 2], zg);
        zo = fmaf(xt, g_Wid[4 * U + 3], zo);
        float cold = g_c[b * cH + U];
        float cn = acc_sig(zf) * cold + acc_sig(zi) * acc_tanh(zg);
        float hn = acc_sig(zo) * acc_tanh(cn);
        g_c[b * cH + U] = cn;
        h_out[b * cH + U] = __float2bfloat16_rn(hn);
    }
}

// ---------------- fused attention ----------------
__global__ __launch_bounds__(512)
void attn_fused(const float* __restrict__ vt_p, int t, float* __restrict__ out,
                const bf16* __restrict__ hb) {
    __shared__ float qs[cH];
    __shared__ float vts[cH];
    __shared__ float sc[cL];
    __shared__ float ajs[cL];
    __shared__ float redm[16];
    __shared__ float reds[16];

    int b = blockIdx.x;
    int tid = threadIdx.x;
    int warp = tid >> 5, lane = tid & 31;

    for (int i = tid; i < cH; i += 512) {
        qs[i]  = g_q[b * cH + i];
        vts[i] = vt_p[i];
    }
    __syncthreads();

    for (int l = warp; l < cL; l += 16) {
        const __nv_bfloat162* row =
            (const __nv_bfloat162*)(g_enc_w1b + (size_t)(b * cL + l) * cH);
        float s = 0.0f;
#pragma unroll 4
        for (int j = lane; j < cH / 2; j += 32) {
            __nv_bfloat162 p = row[j];
            float2 qv = *(const float2*)(qs + 2 * j);
            float2 vv = *(const float2*)(vts + 2 * j);
            s = fmaf(vv.x, mufu_tanh(__bfloat162float(p.x) + qv.x), s);
            s = fmaf(vv.y, mufu_tanh(__bfloat162float(p.y) + qv.y), s);
        }
#pragma unroll
        for (int o = 16; o > 0; o >>= 1) s += __shfl_xor_sync(0xffffffffu, s, o);
        if (lane == 0) sc[l] = s;
    }
    __syncthreads();

    float sval = (tid < cL) ? sc[tid] : -3.0e38f;
    float m = sval;
#pragma unroll
    for (int o = 16; o > 0; o >>= 1) m = fmaxf(m, __shfl_xor_sync(0xffffffffu, m, o));
    if (lane == 0) redm[warp] = m;
    __syncthreads();
    if (tid < 16) {
        float mm = redm[tid];
#pragma unroll
        for (int o = 8; o > 0; o >>= 1) mm = fmaxf(mm, __shfl_xor_sync(0x0000ffffu, mm, o));
        if (tid == 0) redm[0] = mm;
    }
    __syncthreads();
    float mx = redm[0];

    float e = (tid < cL) ? __expf(sval - mx) : 0.0f;
    float ss = e;
#pragma unroll
    for (int o = 16; o > 0; o >>= 1) ss += __shfl_xor_sync(0xffffffffu, ss, o);
    if (lane == 0) reds[warp] = ss;
    __syncthreads();
    if (tid < 16) {
        float s2 = reds[tid];
#pragma unroll
        for (int o = 8; o > 0; o >>= 1) s2 += __shfl_xor_sync(0x0000ffffu, s2, o);
        if (tid == 0) reds[0] = s2;
    }
    __syncthreads();
    float tot = reds[0];

    if (tid < cL) {
        out[((size_t)b * cL + t) * cL + tid] = sval - mx - __logf(tot);
        ajs[tid] = __fdividef(e, tot);
    }
    __syncthreads();

    float acc = 0.0f;
    const bf16* eo = g_enc_outb + (size_t)b * cL * cH + tid;
#pragma unroll 8
    for (int l = 0; l < cL; l++)
        acc = fmaf(ajs[l], __bfloat162float(eo[(size_t)l * cH]), acc);

    g_xcatb[b * KCAT + tid]      = __float2bfloat16_rn(acc);
    g_xcatb[b * KCAT + cH + tid] = hb[b * cH + tid];
}

// ---------------- host orchestration ----------------
extern "C" void kernel_launch(void* const* d_in, const int* in_sizes, int n_in,
                              void* d_out, int out_size) {
    const int*   xs      = (const int*)d_in[0];
    const int*   argsort = (const int*)d_in[2];
    const float* enc_Wi  = (const float*)d_in[3];
    const float* enc_Wh  = (const float*)d_in[4];
    const float* enc_b   = (const float*)d_in[5];
    const float* dec_Wi  = (const float*)d_in[6];
    const float* dec_Wh  = (const float*)d_in[7];
    const float* dec_b   = (const float*)d_in[8];
    const float* w1      = (const float*)d_in[9];
    const float* w2      = (const float*)d_in[10];
    const float* vt      = (const float*)d_in[11];
    float*       out     = (float*)d_out;

    bf16 *ph0, *ph1, *pxcat, *pcatW, *pw2b;
    float *pq, *pbd;
    cudaGetSymbolAddress((void**)&ph0,   g_hb);
    ph1 = ph0 + cB * cH;
    cudaGetSymbolAddress((void**)&pq,    g_q);
    cudaGetSymbolAddress((void**)&pxcat, g_xcatb);
    cudaGetSymbolAddress((void**)&pcatW, g_catW);
    cudaGetSymbolAddress((void**)&pw2b,  g_w2b);
    cudaGetSymbolAddress((void**)&pbd,   g_bd);

    // one-time setup (kept out of graph capture)
    static bool attr_done = false;
    if (!attr_done) {
        cudaFuncSetAttribute(enc_persist, cudaFuncAttributeMaxDynamicSharedMemorySize, 102400);
        attr_done = true;
    }

    prep_kernel<<<2080, 1024>>>(xs, argsort, enc_Wi, enc_Wh, enc_b,
                                dec_Wi, dec_Wh, dec_b, w1, w2);

    // persistent encoder: all 128 steps in one launch (8 warps/block)
    enc_persist<<<NBLK, 256, 102400>>>(xs);

    // enc_w1 = enc_out @ w1^T
    gemm_w1<<<dim3(cH / 64, (cB * cL) / 64), 128>>>();

    // decoder: launch-based, 8-warp GEMMs
    bf16* hb[2] = {ph0, ph1};
    int cur = 0;
    for (int t = 0; t < cL; t++) {
        dec_gemm<<<dim3(cH / 64, cB / 64), 256>>>(
            hb[cur], pw2b, pq, nullptr, nullptr,
            cB, cH, cH, 0, 0);
        attn_fused<<<cB, 512>>>(vt, t, out, hb[cur]);
        dec_gemm<<<dim3(cH4 / 64, cB / 64), 256>>>(
            pxcat, pcatW, nullptr, pbd, hb[cur ^ 1],
            cB, cH4, KCAT, 2, t);
        cur ^= 1;
    }
}